// round 7
// baseline (speedup 1.0000x reference)
#include <cuda_runtime.h>

#define Dd 256
#define Nn 1024
#define Mm 1024
#define NGRP 256              // 4-row column-partial groups (1024/4)
#define K3_BLOCKS 128

typedef unsigned long long u64;
typedef unsigned int u32;

// Scratch (static __device__ — no runtime allocation)
__device__ float g_S[Nn * Mm];            // score matrix s = -L1dist (4 MB)
__device__ float g_pm[Mm * NGRP];         // col partial max, transposed [col][group]
__device__ float g_ps[Mm * NGRP];         // col partial expsum
__device__ float g_cm[Mm], g_cinv[Mm];    // column max, 1/colsum
__device__ float g_num[Nn], g_den[Nn];    // per-row final partials
__device__ u32 g_done = 0;                // k3 last-block counter (self-resetting)

#define FMA2(o, a, b, c) asm("fma.rn.f32x2 %0, %1, %2, %3;" : "=l"(o) : "l"(a), "l"(b), "l"(c))
#define ADD2(o, a, b)    asm("add.rn.f32x2 %0, %1, %2;"     : "=l"(o) : "l"(a), "l"(b))

__device__ __forceinline__ float lo32(u64 v) { return __uint_as_float((u32)v); }
__device__ __forceinline__ float hi32(u64 v) { return __uint_as_float((u32)(v >> 32)); }

__device__ __forceinline__ float warpMax(float v) {
    #pragma unroll
    for (int o = 16; o; o >>= 1) v = fmaxf(v, __shfl_xor_sync(0xffffffffu, v, o));
    return v;
}
__device__ __forceinline__ float warpSum(float v) {
    #pragma unroll
    for (int o = 16; o; o >>= 1) v += __shfl_xor_sync(0xffffffffu, v, o);
    return v;
}

// ===================== K1: scores + per-4-row-group column partials =====================
// 2048 blocks (256 row-quads x 8 col-tiles), 128 threads, 14 blocks/SM resident.
// Warp w owns row i0+w; thread lane owns cols j0+4*lane .. +3.
__global__ __launch_bounds__(128, 14) void k1_scores(
    const float* __restrict__ zx, const float* __restrict__ zy)
{
    __shared__ __align__(8) float2 xs[Dd][4];     // duplicated (x,x), 8 KB
    __shared__ __align__(16) float sbuf[4][128];  // epilogue col-transpose, 2 KB
    const int t = threadIdx.x;
    const int w = t >> 5, lane = t & 31;
    const int rgb = blockIdx.x >> 3;              // row quad [0,256)
    const int ct = blockIdx.x & 7;                // col tile [0,8)
    const int i0 = rgb * 4, j0 = ct * 128;

    for (int idx = t; idx < Dd * 4; idx += 128) {
        int d = idx >> 2, r = idx & 3;
        float v = zx[d * Nn + i0 + r];
        xs[d][r] = make_float2(v, v);
    }
    __syncthreads();

    const u64 NEG1 = 0xBF800000BF800000ULL;
    const u64 ABSM = 0x7FFFFFFF7FFFFFFFULL;

    u64 acc01 = 0, acc23 = 0;                     // cols (j,j+1), (j+2,j+3)
    const ulonglong2* yb = reinterpret_cast<const ulonglong2*>(zy + j0) + lane;  // stride 256/d

    ulonglong2 yA = yb[0];
    ulonglong2 yB = yb[256];

    #pragma unroll 4
    for (int d = 0; d < Dd; d += 2) {
        ulonglong2 yn0 = yA, yn1 = yB;
        if (d + 2 < Dd) yn0 = yb[(size_t)(d + 2) * 256];
        if (d + 3 < Dd) yn1 = yb[(size_t)(d + 3) * 256];
        {
            u64 xd = *reinterpret_cast<const u64*>(&xs[d][w]);
            u64 d0, d1;
            FMA2(d0, yA.x, NEG1, xd);
            FMA2(d1, yA.y, NEG1, xd);
            d0 &= ABSM; d1 &= ABSM;
            ADD2(acc01, acc01, d0);
            ADD2(acc23, acc23, d1);
        }
        {
            u64 xd = *reinterpret_cast<const u64*>(&xs[d + 1][w]);
            u64 d0, d1;
            FMA2(d0, yB.x, NEG1, xd);
            FMA2(d1, yB.y, NEG1, xd);
            d0 &= ABSM; d1 &= ABSM;
            ADD2(acc01, acc01, d0);
            ADD2(acc23, acc23, d1);
        }
        yA = yn0; yB = yn1;
    }

    // Epilogue: s = -dist for 1 row x 4 cols, store coalesced.
    float s0 = -lo32(acc01), s1 = -hi32(acc01);
    float s2 = -lo32(acc23), s3 = -hi32(acc23);
    const int jc = j0 + lane * 4;
    *reinterpret_cast<float4*>(g_S + (size_t)(i0 + w) * Mm + jc) =
        make_float4(s0, s1, s2, s3);

    // Column partials over this block's 4 rows: transpose via smem.
    *reinterpret_cast<float4*>(&sbuf[w][lane * 4]) = make_float4(s0, s1, s2, s3);
    __syncthreads();

    {
        const int c = t;                           // column j0+c
        float v0 = sbuf[0][c], v1 = sbuf[1][c], v2 = sbuf[2][c], v3 = sbuf[3][c];
        float m = fmaxf(fmaxf(v0, v1), fmaxf(v2, v3));
        float e = __expf(v0 - m) + __expf(v1 - m) + __expf(v2 - m) + __expf(v3 - m);
        g_pm[(size_t)(j0 + c) * NGRP + rgb] = m;
        g_ps[(size_t)(j0 + c) * NGRP + rgb] = e;
    }
}

// ===================== K2: combine 256 column partials (warp per column) =====================
__global__ __launch_bounds__(256) void k2_colcombine()
{
    const int w = threadIdx.x >> 5, lane = threadIdx.x & 31;
    const int j = blockIdx.x * 8 + w;
    const float4* pm = reinterpret_cast<const float4*>(g_pm + (size_t)j * NGRP);
    const float4* ps = reinterpret_cast<const float4*>(g_ps + (size_t)j * NGRP);

    float4 m4a = pm[lane * 2], m4b = pm[lane * 2 + 1];
    float m = fmaxf(fmaxf(fmaxf(m4a.x, m4a.y), fmaxf(m4a.z, m4a.w)),
                    fmaxf(fmaxf(m4b.x, m4b.y), fmaxf(m4b.z, m4b.w)));
    m = warpMax(m);

    float4 s4a = ps[lane * 2], s4b = ps[lane * 2 + 1];
    float s = s4a.x * __expf(m4a.x - m) + s4a.y * __expf(m4a.y - m) +
              s4a.z * __expf(m4a.z - m) + s4a.w * __expf(m4a.w - m) +
              s4b.x * __expf(m4b.x - m) + s4b.y * __expf(m4b.y - m) +
              s4b.z * __expf(m4b.z - m) + s4b.w * __expf(m4b.w - m);
    s = warpSum(s);

    if (lane == 0) { g_cm[j] = m; g_cinv[j] = 1.0f / s; }
}

// ===================== K3: warp-per-row final partials + last-block combine =====================
__global__ __launch_bounds__(256) void k3_rows(float* __restrict__ out)
{
    __shared__ float shn[8], shd[8];
    __shared__ u32 sh_last;
    const int t = threadIdx.x;
    const int w = t >> 5, lane = t & 31;
    const int i = blockIdx.x * 8 + w;
    const float4* row = reinterpret_cast<const float4*>(g_S + (size_t)i * Mm);

    float4 s[8];
    float m = -3.4e38f;
    #pragma unroll
    for (int q = 0; q < 8; ++q) {
        s[q] = row[q * 32 + lane];
        m = fmaxf(m, fmaxf(fmaxf(s[q].x, s[q].y), fmaxf(s[q].z, s[q].w)));
    }
    m = warpMax(m);

    float4 e[8];
    float rs = 0.f;
    #pragma unroll
    for (int q = 0; q < 8; ++q) {
        e[q].x = __expf(s[q].x - m); e[q].y = __expf(s[q].y - m);
        e[q].z = __expf(s[q].z - m); e[q].w = __expf(s[q].w - m);
        rs += e[q].x + e[q].y + e[q].z + e[q].w;
    }
    rs = warpSum(rs);
    const float rinv = 1.0f / rs;

    float num = 0.f, den = 0.f;
    #pragma unroll
    for (int q = 0; q < 8; ++q) {
        float4 cm = reinterpret_cast<const float4*>(g_cm)[q * 32 + lane];
        float4 ci = reinterpret_cast<const float4*>(g_cinv)[q * 32 + lane];
        {
            float a = e[q].x * rinv, b = __expf(s[q].x - cm.x) * ci.x;
            float u = a + b - a * b; num += u * s[q].x; den += u;
        }
        {
            float a = e[q].y * rinv, b = __expf(s[q].y - cm.y) * ci.y;
            float u = a + b - a * b; num += u * s[q].y; den += u;
        }
        {
            float a = e[q].z * rinv, b = __expf(s[q].z - cm.z) * ci.z;
            float u = a + b - a * b; num += u * s[q].z; den += u;
        }
        {
            float a = e[q].w * rinv, b = __expf(s[q].w - cm.w) * ci.w;
            float u = a + b - a * b; num += u * s[q].w; den += u;
        }
    }
    num = warpSum(num);
    den = warpSum(den);
    if (lane == 0) { g_num[i] = num; g_den[i] = den; }

    // ---- last-block deterministic combine ----
    __threadfence();
    __syncthreads();
    if (t == 0) sh_last = atomicAdd(&g_done, 1u);
    __syncthreads();
    if (sh_last != K3_BLOCKS - 1) return;

    __threadfence();   // acquire side: see all blocks' g_num/g_den
    float n2 = 0.f, d2 = 0.f;
    #pragma unroll
    for (int p = t; p < Nn; p += 256) { n2 += g_num[p]; d2 += g_den[p]; }
    n2 = warpSum(n2); d2 = warpSum(d2);
    if (lane == 0) { shn[w] = n2; shd[w] = d2; }
    __syncthreads();
    if (w == 0) {
        float n = (lane < 8) ? shn[lane] : 0.f;
        float d = (lane < 8) ? shd[lane] : 0.f;
        n = warpSum(n); d = warpSum(d);
        if (lane == 0) {
            out[0] = n / d;
            g_done = 0;          // self-reset for next graph replay
        }
    }
}

extern "C" void kernel_launch(void* const* d_in, const int* in_sizes, int n_in,
                              void* d_out, int out_size)
{
    const float* zx = (const float*)d_in[0];
    const float* zy = (const float*)d_in[1];
    float* out = (float*)d_out;

    k1_scores<<<2048, 128>>>(zx, zy);
    k2_colcombine<<<Mm / 8, 256>>>();
    k3_rows<<<K3_BLOCKS, 256>>>(out);
}

// round 8
// speedup vs baseline: 1.3661x; 1.3661x over previous
#include <cuda_runtime.h>

#define Dd 256
#define Nn 1024
#define Mm 1024
#define NGRP 128              // 8-row column-partial groups (1024/8)
#define K3_BLOCKS 128

typedef unsigned long long u64;
typedef unsigned int u32;

// Scratch (static __device__ — no runtime allocation)
__device__ float g_S[Nn * Mm];            // score matrix s = -L1dist (4 MB)
__device__ float g_pm[Mm * NGRP];         // col partial max, transposed [col][group]
__device__ float g_ps[Mm * NGRP];         // col partial expsum
__device__ float g_cm[Mm], g_cinv[Mm];    // column max, 1/colsum
__device__ float g_num[Nn], g_den[Nn];    // per-row final partials
__device__ u32 g_done = 0;                // k3 last-block counter (self-resetting)

#define FMA2(o, a, b, c) asm("fma.rn.f32x2 %0, %1, %2, %3;" : "=l"(o) : "l"(a), "l"(b), "l"(c))
#define ADD2(o, a, b)    asm("add.rn.f32x2 %0, %1, %2;"     : "=l"(o) : "l"(a), "l"(b))
#define DUP2(o, r)       asm("mov.b64 %0, {%1,%1};"         : "=l"(o) : "r"(r))

__device__ __forceinline__ float lo32(u64 v) { return __uint_as_float((u32)v); }
__device__ __forceinline__ float hi32(u64 v) { return __uint_as_float((u32)(v >> 32)); }

__device__ __forceinline__ float warpMax(float v) {
    #pragma unroll
    for (int o = 16; o; o >>= 1) v = fmaxf(v, __shfl_xor_sync(0xffffffffu, v, o));
    return v;
}
__device__ __forceinline__ float warpSum(float v) {
    #pragma unroll
    for (int o = 16; o; o >>= 1) v += __shfl_xor_sync(0xffffffffu, v, o);
    return v;
}

// ===================== K1: scores + per-8-row-group column partials =====================
// 512 blocks (128 row-octets x 4 col-quarters), 128 threads = 4 warps.
// Warp w: cols [cb*256 + w*64, +64); lane owns 2 cols. All warps share the block's 8 rows.
// Per lane: 8 u64 accumulators = (row-pair p, col c). x = natural packed pairs from smem
// (broadcast LDS), y duplicated into (y,y) via register MOV — zero extra wavefronts.
__global__ __launch_bounds__(128) void k1_scores(
    const float* __restrict__ zx, const float* __restrict__ zy)
{
    __shared__ __align__(16) u64 xs[Dd + 4][4];   // natural pairs (x[2p],x[2p+1]), ~8.3KB
    const int t = threadIdx.x;
    const int w = t >> 5, lane = t & 31;
    const int rb = blockIdx.x >> 2;               // row octet [0,128)
    const int cb = blockIdx.x & 3;                // col quarter [0,4)
    const int i0 = rb * 8;
    const int jb = cb * 256 + w * 64;             // warp col band

    {
        const u64* zx64 = reinterpret_cast<const u64*>(zx) + (i0 >> 1);
        for (int k = t; k < Dd * 4; k += 128) {
            int d = k >> 2, p = k & 3;
            xs[d][p] = zx64[(size_t)d * 512 + p];
        }
        if (t < 16) xs[Dd + (t >> 2)][t & 3] = 0ULL;   // pad rows 256..259
    }
    __syncthreads();

    const u64 NEG1 = 0xBF800000BF800000ULL;
    const u64 ABSM = 0x7FFFFFFF7FFFFFFFULL;

    u64 accA[4] = {0, 0, 0, 0};                   // col j   : row-pairs 0..3
    u64 accB[4] = {0, 0, 0, 0};                   // col j+1 : row-pairs 0..3

    const u64* yb = reinterpret_cast<const u64*>(zy) + (jb >> 1) + lane;   // stride 512/d

    u64 y0 = yb[0];
    u64 y1 = yb[512];
    ulonglong2 xA0 = *reinterpret_cast<const ulonglong2*>(&xs[0][0]);
    ulonglong2 xA1 = *reinterpret_cast<const ulonglong2*>(&xs[0][2]);
    ulonglong2 xB0 = *reinterpret_cast<const ulonglong2*>(&xs[1][0]);
    ulonglong2 xB1 = *reinterpret_cast<const ulonglong2*>(&xs[1][2]);

    auto step = [&](u64 yc, ulonglong2& X0, ulonglong2& X1, int dpre) {
        u64 yd0, yd1;
        DUP2(yd0, (u32)yc);
        DUP2(yd1, (u32)(yc >> 32));
        u64 t0, t1, t2, t3, t4, t5, t6, t7;
        FMA2(t0, yd0, NEG1, X0.x);
        FMA2(t1, yd1, NEG1, X0.x);
        FMA2(t2, yd0, NEG1, X0.y);
        FMA2(t3, yd1, NEG1, X0.y);
        FMA2(t4, yd0, NEG1, X1.x);
        FMA2(t5, yd1, NEG1, X1.x);
        FMA2(t6, yd0, NEG1, X1.y);
        FMA2(t7, yd1, NEG1, X1.y);
        X0 = *reinterpret_cast<const ulonglong2*>(&xs[dpre][0]);   // refill 2 d ahead
        X1 = *reinterpret_cast<const ulonglong2*>(&xs[dpre][2]);
        t0 &= ABSM; t1 &= ABSM; t2 &= ABSM; t3 &= ABSM;
        t4 &= ABSM; t5 &= ABSM; t6 &= ABSM; t7 &= ABSM;
        ADD2(accA[0], accA[0], t0);
        ADD2(accB[0], accB[0], t1);
        ADD2(accA[1], accA[1], t2);
        ADD2(accB[1], accB[1], t3);
        ADD2(accA[2], accA[2], t4);
        ADD2(accB[2], accB[2], t5);
        ADD2(accA[3], accA[3], t6);
        ADD2(accB[3], accB[3], t7);
    };

    #pragma unroll 2
    for (int d = 0; d < Dd; d += 2) {
        u64 yc0 = y0, yc1 = y1;
        int dn0 = (d + 2 < Dd) ? d + 2 : Dd - 1;   // clamped — no branch, no OOB
        int dn1 = (d + 3 < Dd) ? d + 3 : Dd - 1;
        y0 = yb[(size_t)dn0 * 512];
        y1 = yb[(size_t)dn1 * 512];
        step(yc0, xA0, xA1, d + 2);
        step(yc1, xB0, xB1, d + 3);
    }

    // Epilogue: s = -dist for 8 rows x 2 cols; store + column partials over the 8 rows.
    const int j = jb + lane * 2;
    float vA[8], vB[8];
    #pragma unroll
    for (int p = 0; p < 4; ++p) {
        vA[2 * p] = -lo32(accA[p]); vA[2 * p + 1] = -hi32(accA[p]);
        vB[2 * p] = -lo32(accB[p]); vB[2 * p + 1] = -hi32(accB[p]);
    }
    #pragma unroll
    for (int r = 0; r < 8; ++r)
        *reinterpret_cast<float2*>(g_S + (size_t)(i0 + r) * Mm + j) =
            make_float2(vA[r], vB[r]);

    float mA = vA[0], mB = vB[0];
    #pragma unroll
    for (int r = 1; r < 8; ++r) { mA = fmaxf(mA, vA[r]); mB = fmaxf(mB, vB[r]); }
    float eA = 0.f, eB = 0.f;
    #pragma unroll
    for (int r = 0; r < 8; ++r) { eA += __expf(vA[r] - mA); eB += __expf(vB[r] - mB); }

    g_pm[(size_t)j * NGRP + rb] = mA;
    g_pm[(size_t)(j + 1) * NGRP + rb] = mB;
    g_ps[(size_t)j * NGRP + rb] = eA;
    g_ps[(size_t)(j + 1) * NGRP + rb] = eB;
}

// ===================== K2: combine 128 column partials (warp per column) =====================
__global__ __launch_bounds__(256) void k2_colcombine()
{
    const int w = threadIdx.x >> 5, lane = threadIdx.x & 31;
    const int j = blockIdx.x * 8 + w;
    const float4 m4 = reinterpret_cast<const float4*>(g_pm + (size_t)j * NGRP)[lane];
    const float4 s4 = reinterpret_cast<const float4*>(g_ps + (size_t)j * NGRP)[lane];

    float m = fmaxf(fmaxf(m4.x, m4.y), fmaxf(m4.z, m4.w));
    m = warpMax(m);

    float s = s4.x * __expf(m4.x - m) + s4.y * __expf(m4.y - m) +
              s4.z * __expf(m4.z - m) + s4.w * __expf(m4.w - m);
    s = warpSum(s);

    if (lane == 0) { g_cm[j] = m; g_cinv[j] = 1.0f / s; }
}

// ===================== K3: warp-per-row final partials + last-block combine =====================
__global__ __launch_bounds__(256) void k3_rows(float* __restrict__ out)
{
    __shared__ float shn[8], shd[8];
    __shared__ u32 sh_last;
    const int t = threadIdx.x;
    const int w = t >> 5, lane = t & 31;
    const int i = blockIdx.x * 8 + w;
    const float4* row = reinterpret_cast<const float4*>(g_S + (size_t)i * Mm);

    float4 s[8];
    float m = -3.4e38f;
    #pragma unroll
    for (int q = 0; q < 8; ++q) {
        s[q] = row[q * 32 + lane];
        m = fmaxf(m, fmaxf(fmaxf(s[q].x, s[q].y), fmaxf(s[q].z, s[q].w)));
    }
    m = warpMax(m);

    float4 e[8];
    float rs = 0.f;
    #pragma unroll
    for (int q = 0; q < 8; ++q) {
        e[q].x = __expf(s[q].x - m); e[q].y = __expf(s[q].y - m);
        e[q].z = __expf(s[q].z - m); e[q].w = __expf(s[q].w - m);
        rs += e[q].x + e[q].y + e[q].z + e[q].w;
    }
    rs = warpSum(rs);
    const float rinv = 1.0f / rs;

    float num = 0.f, den = 0.f;
    #pragma unroll
    for (int q = 0; q < 8; ++q) {
        float4 cm = reinterpret_cast<const float4*>(g_cm)[q * 32 + lane];
        float4 ci = reinterpret_cast<const float4*>(g_cinv)[q * 32 + lane];
        {
            float a = e[q].x * rinv, b = __expf(s[q].x - cm.x) * ci.x;
            float u = a + b - a * b; num += u * s[q].x; den += u;
        }
        {
            float a = e[q].y * rinv, b = __expf(s[q].y - cm.y) * ci.y;
            float u = a + b - a * b; num += u * s[q].y; den += u;
        }
        {
            float a = e[q].z * rinv, b = __expf(s[q].z - cm.z) * ci.z;
            float u = a + b - a * b; num += u * s[q].z; den += u;
        }
        {
            float a = e[q].w * rinv, b = __expf(s[q].w - cm.w) * ci.w;
            float u = a + b - a * b; num += u * s[q].w; den += u;
        }
    }
    num = warpSum(num);
    den = warpSum(den);
    if (lane == 0) { g_num[i] = num; g_den[i] = den; }

    // ---- last-block deterministic combine ----
    __threadfence();
    __syncthreads();
    if (t == 0) sh_last = atomicAdd(&g_done, 1u);
    __syncthreads();
    if (sh_last != K3_BLOCKS - 1) return;

    __threadfence();   // acquire side: see all blocks' g_num/g_den
    float n2 = 0.f, d2 = 0.f;
    #pragma unroll
    for (int p = t; p < Nn; p += 256) { n2 += g_num[p]; d2 += g_den[p]; }
    n2 = warpSum(n2); d2 = warpSum(d2);
    if (lane == 0) { shn[w] = n2; shd[w] = d2; }
    __syncthreads();
    if (w == 0) {
        float n = (lane < 8) ? shn[lane] : 0.f;
        float d = (lane < 8) ? shd[lane] : 0.f;
        n = warpSum(n); d = warpSum(d);
        if (lane == 0) {
            out[0] = n / d;
            g_done = 0;          // self-reset for next graph replay
        }
    }
}

extern "C" void kernel_launch(void* const* d_in, const int* in_sizes, int n_in,
                              void* d_out, int out_size)
{
    const float* zx = (const float*)d_in[0];
    const float* zy = (const float*)d_in[1];
    float* out = (float*)d_out;

    k1_scores<<<512, 128>>>(zx, zy);
    k2_colcombine<<<Mm / 8, 256>>>();
    k3_rows<<<K3_BLOCKS, 256>>>(out);
}